// round 14
// baseline (speedup 1.0000x reference)
#include <cuda_runtime.h>
#include <cstdint>

#define D       28
#define EMB     784
#define MATB    (EMB * 4)    // 3136 bytes per matrix
#define SLEN    64
#define HALF    16           // words per chain (2 chains of 16 per warp = half sentence)
#define NW      2            // warps per block
#define NBATCH  2048
#define REPS    2            // sentences per block
#define GRID    (NBATCH / REPS)   // 1024 blocks -> single wave (cap 1184)

// Per-warp smem: 4 matrix slots of exactly 784 floats (3136 B), contiguous,
// order A0,B0,A1,B1. 3136 mod 128 == 64, so the chain-B base is offset
// 64 mod 128 from chain-A within each parity: the two broadcast addresses of
// a dual LDS.128 hit disjoint bank groups -> conflict-free.

// ---- packed f32x2 helpers (Blackwell FFMA2 path, PTX-only) ----
__device__ __forceinline__ unsigned long long ffma2(unsigned long long a,
                                                    unsigned long long b,
                                                    unsigned long long c) {
    unsigned long long d;
    asm("fma.rn.f32x2 %0, %1, %2, %3;" : "=l"(d) : "l"(a), "l"(b), "l"(c));
    return d;
}
__device__ __forceinline__ unsigned long long pack2(float x, float y) {
    unsigned long long d;
    asm("mov.b64 %0, {%1, %2};" : "=l"(d) : "f"(x), "f"(y));
    return d;
}
__device__ __forceinline__ void unpack2(unsigned long long v, float& x, float& y) {
    asm("mov.b64 {%0, %1}, %2;" : "=f"(x), "=f"(y) : "l"(v));
}

__device__ __forceinline__ unsigned smem_u32(const void* p) {
    return (unsigned)__cvta_generic_to_shared(p);
}
__device__ __forceinline__ void mbar_init(unsigned a, unsigned cnt) {
    asm volatile("mbarrier.init.shared.b64 [%0], %1;" :: "r"(a), "r"(cnt) : "memory");
}
__device__ __forceinline__ void mbar_expect_tx(unsigned a, unsigned bytes) {
    asm volatile("mbarrier.arrive.expect_tx.shared.b64 _, [%0], %1;"
                 :: "r"(a), "r"(bytes) : "memory");
}
__device__ __forceinline__ void bulk_g2s(unsigned dst, const void* src, unsigned bytes,
                                         unsigned mbar) {
    asm volatile("cp.async.bulk.shared::cta.global.mbarrier::complete_tx::bytes "
                 "[%0], [%1], %2, [%3];"
                 :: "r"(dst), "l"(src), "r"(bytes), "r"(mbar) : "memory");
}
__device__ __forceinline__ void mbar_wait(unsigned a, unsigned parity) {
    unsigned done;
    asm volatile(
        "{\n\t.reg .pred p;\n\t"
        "mbarrier.try_wait.parity.shared.b64 p, [%1], %2;\n\t"
        "selp.b32 %0, 1, 0, p;\n\t}"
        : "=r"(done) : "r"(a), "r"(parity) : "memory");
    while (!done) {
        asm volatile(
            "{\n\t.reg .pred p;\n\t"
            "mbarrier.try_wait.parity.shared.b64 p, [%1], %2, 0x989680;\n\t"
            "selp.b32 %0, 1, 0, p;\n\t}"
            : "=r"(done) : "r"(a), "r"(parity) : "memory");
    }
}

// Dual-row matmul step, software-pipelined loads (best measured engine).
__device__ __forceinline__ void mat_mul_dual(float c0[D], float c1[D],
                                             const float* __restrict__ m) {
    unsigned long long a0[D / 2], a1[D / 2];
    ulonglong2 mv[7];
    #pragma unroll
    for (int t = 0; t < 7; t++) mv[t] = ((const ulonglong2*)m)[t];     // row k=0
    #pragma unroll
    for (int j = 0; j < D / 2; j++) { a0[j] = 0ULL; a1[j] = 0ULL; }

    #pragma unroll
    for (int k = 0; k < D; k++) {
        const unsigned long long k0 = pack2(c0[k], c0[k]);
        const unsigned long long k1 = pack2(c1[k], c1[k]);
        const ulonglong2* nxt = (const ulonglong2*)(m + (k + 1) * D);
        #pragma unroll
        for (int t = 0; t < 7; t++) {
            const ulonglong2 cur = mv[t];
            if (k < D - 1) mv[t] = nxt[t];          // prefetch row k+1, slot t
            a0[2*t]     = ffma2(k0, cur.x, a0[2*t]);
            a0[2*t + 1] = ffma2(k0, cur.y, a0[2*t + 1]);
            a1[2*t]     = ffma2(k1, cur.x, a1[2*t]);
            a1[2*t + 1] = ffma2(k1, cur.y, a1[2*t + 1]);
        }
    }
    #pragma unroll
    for (int j = 0; j < D / 2; j++) {
        unpack2(a0[j], c0[2*j], c0[2*j + 1]);
        unpack2(a1[j], c1[2*j], c1[2*j + 1]);
    }
}

// Mono matmul (row per lane, uniform broadcast of M from smem).
__device__ __forceinline__ void mat_mul_row(float c[D], const float* __restrict__ m,
                                            int lane) {
    if (lane < D) {
        unsigned long long acc[D / 2];
        #pragma unroll
        for (int j = 0; j < D / 2; j++) acc[j] = 0ULL;
        #pragma unroll
        for (int k = 0; k < D; k++) {
            const unsigned long long ck = pack2(c[k], c[k]);
            const ulonglong2* mr = (const ulonglong2*)(m + k * D);
            #pragma unroll
            for (int t = 0; t < 7; t++) {
                ulonglong2 mv = mr[t];
                acc[2*t]     = ffma2(ck, mv.x, acc[2*t]);
                acc[2*t + 1] = ffma2(ck, mv.y, acc[2*t + 1]);
            }
        }
        #pragma unroll
        for (int j = 0; j < D / 2; j++) unpack2(acc[j], c[2*j], c[2*j + 1]);
    }
}

// Partial mono over j-chunks [TLO, THI): columns [4*TLO, 4*THI) of row `lane`
// of (c @ M), stored straight to orow (16B-aligned chunks).
template <int TLO, int THI>
__device__ __forceinline__ void mat_mul_row_part(const float c[D],
                                                 const float* __restrict__ m,
                                                 float* __restrict__ orow, int lane) {
    if (lane < D) {
        unsigned long long acc[2 * (THI - TLO)];
        #pragma unroll
        for (int j = 0; j < 2 * (THI - TLO); j++) acc[j] = 0ULL;
        #pragma unroll
        for (int k = 0; k < D; k++) {
            const unsigned long long ck = pack2(c[k], c[k]);
            const ulonglong2* mr = (const ulonglong2*)(m + k * D);
            #pragma unroll
            for (int t = TLO; t < THI; t++) {
                ulonglong2 mv = mr[t];
                acc[2*(t-TLO)]     = ffma2(ck, mv.x, acc[2*(t-TLO)]);
                acc[2*(t-TLO) + 1] = ffma2(ck, mv.y, acc[2*(t-TLO) + 1]);
            }
        }
        #pragma unroll
        for (int t = TLO; t < THI; t++) {
            float x0, x1, x2, x3;
            unpack2(acc[2*(t-TLO)],     x0, x1);
            unpack2(acc[2*(t-TLO) + 1], x2, x3);
            *(float4*)(orow + 4 * t) = make_float4(x0, x1, x2, x3);
        }
    }
}

// publish this lane's two chain-result rows into an smem matrix slot
__device__ __forceinline__ void publish_dual(const float c0[D], const float c1[D],
                                             float* dst, int g) {
    float* r0 = dst + g * D;
    float* r1 = dst + (g + 14) * D;
    #pragma unroll
    for (int t = 0; t < 7; t++) {
        *(float4*)(r0 + 4 * t) = make_float4(c0[4*t], c0[4*t+1], c0[4*t+2], c0[4*t+3]);
        *(float4*)(r1 + 4 * t) = make_float4(c1[4*t], c1[4*t+1], c1[4*t+2], c1[4*t+3]);
    }
}

// publish this lane's single row (mono result) into an smem matrix slot
__device__ __forceinline__ void store_rows(const float c[D], float* dst, int lane) {
    if (lane < D) {
        float* o = dst + lane * D;
        #pragma unroll
        for (int t = 0; t < 7; t++)
            *(float4*)(o + 4 * t) = make_float4(c[4*t], c[4*t+1], c[4*t+2], c[4*t+3]);
    }
}

// ---- fused kernel: 1024 blocks x 2 warps; 2 sentences per block (single wave) ----
__global__ __launch_bounds__(NW * 32, 8)
void w2m_fused_kernel(const float* __restrict__ table,
                      const int*   __restrict__ sent,
                      float*       __restrict__ out) {
    // [warp][slot][784]: slot order A0,B0,A1,B1 (3136 B apart -> 64 mod 128)
    __shared__ __align__(16) float sm[NW][4][EMB];
    __shared__ __align__(8)  unsigned long long mbar[NW][2];

    const int tid  = threadIdx.x;
    const int warp = tid >> 5;
    const int lane = tid & 31;

    if (tid < NW * 2) mbar_init(smem_u32(&mbar[tid >> 1][tid & 1]), 1);
    __syncthreads();

    const int  grp   = (lane >= 14) ? 1 : 0;                 // 0: chain A, 1: chain B
    const int  g     = (lane < 14) ? lane : (lane < 28 ? lane - 14 : 0);
    const bool valid = (lane < 28);
    float (* const wsm)[EMB] = sm[warp];

    int ph0 = 0, ph1 = 0;    // mbar phase parity persists across sentences

    #pragma unroll 1
    for (int rep = 0; rep < REPS; ++rep) {
        const int b   = blockIdx.x * REPS + rep;
        const int* si = sent + b * SLEN + warp * 32;   // 32 words: 2 chains of 16

        // ---- init: cur = first matrix of the chain (rows g and g+14) ----
        float c0[D], c1[D];
        {
            const float* src = table + (size_t)(grp ? si[HALF] : si[0]) * EMB;
            const float* p0 = src + g * D;
            const float* p1 = p0 + 14 * D;
            #pragma unroll
            for (int t = 0; t < 7; t++) {
                float4 v0 = __ldg((const float4*)(p0 + 4 * t));
                float4 v1 = __ldg((const float4*)(p1 + 4 * t));
                c0[4*t] = v0.x; c0[4*t+1] = v0.y; c0[4*t+2] = v0.z; c0[4*t+3] = v0.w;
                c1[4*t] = v1.x; c1[4*t+1] = v1.y; c1[4*t+2] = v1.z; c1[4*t+3] = v1.w;
            }
        }

        // ---- prologue: prefetch step-1 matrices (both chains) into parity-1 slots ----
        if (lane == 0) {
            const unsigned mb = smem_u32(&mbar[warp][1]);
            mbar_expect_tx(mb, 2 * MATB);
            bulk_g2s(smem_u32(wsm[2]), table + (size_t)si[1] * EMB, MATB, mb);
            bulk_g2s(smem_u32(wsm[3]), table + (size_t)si[HALF + 1] * EMB, MATB, mb);
        }

        #pragma unroll 1
        for (int s = 1; s < HALF; ++s) {
            const int par = s & 1;
            if (s + 1 < HALF && lane == 0) {
                const int np = (s + 1) & 1;
                const unsigned mb = smem_u32(&mbar[warp][np]);
                mbar_expect_tx(mb, 2 * MATB);
                bulk_g2s(smem_u32(wsm[np ? 2 : 0]),
                         table + (size_t)si[s + 1] * EMB, MATB, mb);
                bulk_g2s(smem_u32(wsm[np ? 3 : 1]),
                         table + (size_t)si[HALF + s + 1] * EMB, MATB, mb);
            }
            if (par) { mbar_wait(smem_u32(&mbar[warp][1]), ph1); ph1 ^= 1; }
            else     { mbar_wait(smem_u32(&mbar[warp][0]), ph0); ph0 ^= 1; }

            const float* m = wsm[(par ? 2 : 0) + grp];   // A: slot 0/2, B: slot 1/3
            mat_mul_dual(c0, c1, m);
            __syncwarp();
        }

        // ---- intra-warp tail: P_w = P_chainA @ P_chainB (mono) ----
        // last dual step s=15 (odd) read parity-1 slots (2,3) -> slots 0,1 free
        if (valid) publish_dual(c0, c1, wsm[grp], g);    // A -> slot0, B -> slot1
        __syncwarp();

        float c[D];
        if (lane < D) {
            const float* p = wsm[0] + lane * D;
            #pragma unroll
            for (int t = 0; t < 7; t++) {
                float4 v = *(const float4*)(p + 4 * t);
                c[4*t] = v.x; c[4*t+1] = v.y; c[4*t+2] = v.z; c[4*t+3] = v.w;
            }
        }
        mat_mul_row(c, wsm[1], lane);                    // c = P_w (row `lane`)

        // ---- in-block combine, column-split across warps: out = P_0 @ P_1 ----
        store_rows(c, wsm[2], lane);                     // P_w -> own slot 2
        __syncthreads();

        float* const orow = out + (size_t)b * EMB + lane * D;
        if (warp == 0) {
            // warp 0: has P_0 row `lane` in c; columns 0..15 against P_1
            mat_mul_row_part<0, 4>(c, sm[1][2], orow, lane);
        } else {
            // warp 1: load P_0 row `lane`, columns 16..27 against P_1 (own slot)
            float cp[D];
            if (lane < D) {
                const float* p = sm[0][2] + lane * D;
                #pragma unroll
                for (int t = 0; t < 7; t++) {
                    float4 v = *(const float4*)(p + 4 * t);
                    cp[4*t] = v.x; cp[4*t+1] = v.y; cp[4*t+2] = v.z; cp[4*t+3] = v.w;
                }
            }
            mat_mul_row_part<4, 7>(cp, sm[1][2], orow, lane);
        }

        // cross-warp slot-2 reads must finish before next rep's TMA overwrites it
        __syncthreads();
    }
}

extern "C" void kernel_launch(void* const* d_in, const int* in_sizes, int n_in,
                              void* d_out, int out_size) {
    const float* table = (const float*)d_in[0];   // [32001, 784] fp32
    const int*   sent  = (const int*)d_in[1];     // [2048, 64]  int32
    float*       out   = (float*)d_out;           // [2048, 784] fp32

    w2m_fused_kernel<<<GRID, NW * 32>>>(table, sent, out);
}

// round 15
// speedup vs baseline: 1.1140x; 1.1140x over previous
#include <cuda_runtime.h>
#include <cstdint>

#define D       28
#define EMB     784
#define MATB    (EMB * 4)    // 3136 bytes per matrix
#define SLEN    64
#define HALF    16           // words per chain (2 chains of 16 per warp = half sentence)
#define NW      2            // warps per block (one sentence per block)
#define NBATCH  2048

// Per-warp smem: 4 matrix slots of exactly 784 floats (3136 B), contiguous,
// order A0,B0,A1,B1. 3136 mod 128 == 64, so the chain-B base is offset
// 64 mod 128 from chain-A within each parity: the two broadcast addresses of
// a dual LDS.128 hit disjoint bank groups -> conflict-free.
// slot index: parity 0 -> A=0,B=1 ; parity 1 -> A=2,B=3

// ---- packed f32x2 helpers (Blackwell FFMA2 path, PTX-only) ----
__device__ __forceinline__ unsigned long long ffma2(unsigned long long a,
                                                    unsigned long long b,
                                                    unsigned long long c) {
    unsigned long long d;
    asm("fma.rn.f32x2 %0, %1, %2, %3;" : "=l"(d) : "l"(a), "l"(b), "l"(c));
    return d;
}
__device__ __forceinline__ unsigned long long pack2(float x, float y) {
    unsigned long long d;
    asm("mov.b64 %0, {%1, %2};" : "=l"(d) : "f"(x), "f"(y));
    return d;
}
__device__ __forceinline__ void unpack2(unsigned long long v, float& x, float& y) {
    asm("mov.b64 {%0, %1}, %2;" : "=f"(x), "=f"(y) : "l"(v));
}

__device__ __forceinline__ unsigned smem_u32(const void* p) {
    return (unsigned)__cvta_generic_to_shared(p);
}
__device__ __forceinline__ void mbar_init(unsigned a, unsigned cnt) {
    asm volatile("mbarrier.init.shared.b64 [%0], %1;" :: "r"(a), "r"(cnt) : "memory");
}
__device__ __forceinline__ void mbar_expect_tx(unsigned a, unsigned bytes) {
    asm volatile("mbarrier.arrive.expect_tx.shared.b64 _, [%0], %1;"
                 :: "r"(a), "r"(bytes) : "memory");
}
__device__ __forceinline__ void bulk_g2s(unsigned dst, const void* src, unsigned bytes,
                                         unsigned mbar) {
    asm volatile("cp.async.bulk.shared::cta.global.mbarrier::complete_tx::bytes "
                 "[%0], [%1], %2, [%3];"
                 :: "r"(dst), "l"(src), "r"(bytes), "r"(mbar) : "memory");
}
__device__ __forceinline__ void mbar_wait(unsigned a, unsigned parity) {
    unsigned done;
    asm volatile(
        "{\n\t.reg .pred p;\n\t"
        "mbarrier.try_wait.parity.shared.b64 p, [%1], %2;\n\t"
        "selp.b32 %0, 1, 0, p;\n\t}"
        : "=r"(done) : "r"(a), "r"(parity) : "memory");
    while (!done) {
        asm volatile(
            "{\n\t.reg .pred p;\n\t"
            "mbarrier.try_wait.parity.shared.b64 p, [%1], %2, 0x989680;\n\t"
            "selp.b32 %0, 1, 0, p;\n\t}"
            : "=r"(done) : "r"(a), "r"(parity) : "memory");
    }
}

// Dual-row matmul step, software-pipelined loads (best measured engine).
__device__ __forceinline__ void mat_mul_dual(float c0[D], float c1[D],
                                             const float* __restrict__ m) {
    unsigned long long a0[D / 2], a1[D / 2];
    ulonglong2 mv[7];
    #pragma unroll
    for (int t = 0; t < 7; t++) mv[t] = ((const ulonglong2*)m)[t];     // row k=0
    #pragma unroll
    for (int j = 0; j < D / 2; j++) { a0[j] = 0ULL; a1[j] = 0ULL; }

    #pragma unroll
    for (int k = 0; k < D; k++) {
        const unsigned long long k0 = pack2(c0[k], c0[k]);
        const unsigned long long k1 = pack2(c1[k], c1[k]);
        const ulonglong2* nxt = (const ulonglong2*)(m + (k + 1) * D);
        #pragma unroll
        for (int t = 0; t < 7; t++) {
            const ulonglong2 cur = mv[t];
            if (k < D - 1) mv[t] = nxt[t];          // prefetch row k+1, slot t
            a0[2*t]     = ffma2(k0, cur.x, a0[2*t]);
            a0[2*t + 1] = ffma2(k0, cur.y, a0[2*t + 1]);
            a1[2*t]     = ffma2(k1, cur.x, a1[2*t]);
            a1[2*t + 1] = ffma2(k1, cur.y, a1[2*t + 1]);
        }
    }
    #pragma unroll
    for (int j = 0; j < D / 2; j++) {
        unpack2(a0[j], c0[2*j], c0[2*j + 1]);
        unpack2(a1[j], c1[2*j], c1[2*j + 1]);
    }
}

// Mono matmul (row per lane, uniform broadcast of M from smem).
__device__ __forceinline__ void mat_mul_row(float c[D], const float* __restrict__ m,
                                            int lane) {
    if (lane < D) {
        unsigned long long acc[D / 2];
        #pragma unroll
        for (int j = 0; j < D / 2; j++) acc[j] = 0ULL;
        #pragma unroll
        for (int k = 0; k < D; k++) {
            const unsigned long long ck = pack2(c[k], c[k]);
            const ulonglong2* mr = (const ulonglong2*)(m + k * D);
            #pragma unroll
            for (int t = 0; t < 7; t++) {
                ulonglong2 mv = mr[t];
                acc[2*t]     = ffma2(ck, mv.x, acc[2*t]);
                acc[2*t + 1] = ffma2(ck, mv.y, acc[2*t + 1]);
            }
        }
        #pragma unroll
        for (int j = 0; j < D / 2; j++) unpack2(acc[j], c[2*j], c[2*j + 1]);
    }
}

// Partial mono over j-chunks [TLO, THI): columns [4*TLO, 4*THI) of row `lane`
// of (c @ M), stored straight to orow (16B-aligned chunks).
template <int TLO, int THI>
__device__ __forceinline__ void mat_mul_row_part(const float c[D],
                                                 const float* __restrict__ m,
                                                 float* __restrict__ orow, int lane) {
    if (lane < D) {
        unsigned long long acc[2 * (THI - TLO)];
        #pragma unroll
        for (int j = 0; j < 2 * (THI - TLO); j++) acc[j] = 0ULL;
        #pragma unroll
        for (int k = 0; k < D; k++) {
            const unsigned long long ck = pack2(c[k], c[k]);
            const ulonglong2* mr = (const ulonglong2*)(m + k * D);
            #pragma unroll
            for (int t = TLO; t < THI; t++) {
                ulonglong2 mv = mr[t];
                acc[2*(t-TLO)]     = ffma2(ck, mv.x, acc[2*(t-TLO)]);
                acc[2*(t-TLO) + 1] = ffma2(ck, mv.y, acc[2*(t-TLO) + 1]);
            }
        }
        #pragma unroll
        for (int t = TLO; t < THI; t++) {
            float x0, x1, x2, x3;
            unpack2(acc[2*(t-TLO)],     x0, x1);
            unpack2(acc[2*(t-TLO) + 1], x2, x3);
            *(float4*)(orow + 4 * t) = make_float4(x0, x1, x2, x3);
        }
    }
}

// publish this lane's two chain-result rows into an smem matrix slot
__device__ __forceinline__ void publish_dual(const float c0[D], const float c1[D],
                                             float* dst, int g) {
    float* r0 = dst + g * D;
    float* r1 = dst + (g + 14) * D;
    #pragma unroll
    for (int t = 0; t < 7; t++) {
        *(float4*)(r0 + 4 * t) = make_float4(c0[4*t], c0[4*t+1], c0[4*t+2], c0[4*t+3]);
        *(float4*)(r1 + 4 * t) = make_float4(c1[4*t], c1[4*t+1], c1[4*t+2], c1[4*t+3]);
    }
}

// publish this lane's single row (mono result) into an smem matrix slot
__device__ __forceinline__ void store_rows(const float c[D], float* dst, int lane) {
    if (lane < D) {
        float* o = dst + lane * D;
        #pragma unroll
        for (int t = 0; t < 7; t++)
            *(float4*)(o + 4 * t) = make_float4(c[4*t], c[4*t+1], c[4*t+2], c[4*t+3]);
    }
}

// ---- fused kernel: 2048 blocks x 2 warps; warp = half-sentence, in-block combine ----
__global__ __launch_bounds__(NW * 32, 8)
void w2m_fused_kernel(const float* __restrict__ table,
                      const int*   __restrict__ sent,
                      float*       __restrict__ out) {
    // [warp][slot][784]: slot order A0,B0,A1,B1 (3136 B apart -> 64 mod 128)
    __shared__ __align__(16) float sm[NW][4][EMB];
    __shared__ __align__(8)  unsigned long long mbar[NW][2];

    const int tid  = threadIdx.x;
    const int warp = tid >> 5;
    const int lane = tid & 31;
    const int b    = blockIdx.x;
    const int* si  = sent + b * SLEN + warp * 32;   // 32 words: 2 chains of 16

    if (tid < NW * 2) mbar_init(smem_u32(&mbar[tid >> 1][tid & 1]), 1);
    __syncthreads();

    const int  grp   = (lane >= 14) ? 1 : 0;                 // 0: chain A, 1: chain B
    const int  g     = (lane < 14) ? lane : (lane < 28 ? lane - 14 : 0);
    const bool valid = (lane < 28);
    float (* const wsm)[EMB] = sm[warp];

    // hoisted mbar addresses (uniform per warp)
    const unsigned mb0 = smem_u32(&mbar[warp][0]);
    const unsigned mb1 = smem_u32(&mbar[warp][1]);

    // ---- init: cur = first matrix of the chain (rows g and g+14) ----
    float c0[D], c1[D];
    {
        const float* src = table + (size_t)(grp ? si[HALF] : si[0]) * EMB;
        const float* p0 = src + g * D;
        const float* p1 = p0 + 14 * D;
        #pragma unroll
        for (int t = 0; t < 7; t++) {
            float4 v0 = __ldg((const float4*)(p0 + 4 * t));
            float4 v1 = __ldg((const float4*)(p1 + 4 * t));
            c0[4*t] = v0.x; c0[4*t+1] = v0.y; c0[4*t+2] = v0.z; c0[4*t+3] = v0.w;
            c1[4*t] = v1.x; c1[4*t+1] = v1.y; c1[4*t+2] = v1.z; c1[4*t+3] = v1.w;
        }
    }

    // ---- prologue: prefetch step-1 matrices (both chains) into parity-1 slots ----
    if (lane == 0) {
        mbar_expect_tx(mb1, 2 * MATB);
        bulk_g2s(smem_u32(wsm[2]), table + (size_t)si[1] * EMB, MATB, mb1);
        bulk_g2s(smem_u32(wsm[3]), table + (size_t)si[HALF + 1] * EMB, MATB, mb1);
    }

    int ph0 = 0, ph1 = 0;
    #pragma unroll 2
    for (int s = 1; s < HALF; ++s) {
        const int par = s & 1;
        if (s + 1 < HALF && lane == 0) {
            const int np = (s + 1) & 1;
            const unsigned mb = np ? mb1 : mb0;
            mbar_expect_tx(mb, 2 * MATB);
            bulk_g2s(smem_u32(wsm[np ? 2 : 0]),
                     table + (size_t)si[s + 1] * EMB, MATB, mb);
            bulk_g2s(smem_u32(wsm[np ? 3 : 1]),
                     table + (size_t)si[HALF + s + 1] * EMB, MATB, mb);
        }
        if (par) { mbar_wait(mb1, ph1); ph1 ^= 1; }
        else     { mbar_wait(mb0, ph0); ph0 ^= 1; }

        const float* m = wsm[(par ? 2 : 0) + grp];   // A: slot 0/2, B: slot 1/3
        mat_mul_dual(c0, c1, m);
        __syncwarp();
    }

    // ---- intra-warp tail: P_w = P_chainA @ P_chainB (mono) ----
    // last dual step s=15 (odd) read parity-1 slots (2,3) -> slots 0,1 free
    if (valid) publish_dual(c0, c1, wsm[grp], g);    // A -> slot0, B -> slot1
    __syncwarp();

    float c[D];
    if (lane < D) {
        const float* p = wsm[0] + lane * D;
        #pragma unroll
        for (int t = 0; t < 7; t++) {
            float4 v = *(const float4*)(p + 4 * t);
            c[4*t] = v.x; c[4*t+1] = v.y; c[4*t+2] = v.z; c[4*t+3] = v.w;
        }
    }
    mat_mul_row(c, wsm[1], lane);                    // c = P_w (row `lane`)

    // ---- in-block combine, column-split across warps: out = P_0 @ P_1 ----
    // Both warps publish P_w into their own slot 2 (free after step 15).
    store_rows(c, wsm[2], lane);
    __syncthreads();

    float* const orow = out + (size_t)b * EMB + lane * D;
    if (warp == 0) {
        // warp 0: has P_0 row `lane` in c; columns 0..15 against P_1
        mat_mul_row_part<0, 4>(c, sm[1][2], orow, lane);
    } else {
        // warp 1: load P_0 row `lane`, columns 16..27 against P_1 (own slot)
        float cp[D];
        if (lane < D) {
            const float* p = sm[0][2] + lane * D;
            #pragma unroll
            for (int t = 0; t < 7; t++) {
                float4 v = *(const float4*)(p + 4 * t);
                cp[4*t] = v.x; cp[4*t+1] = v.y; cp[4*t+2] = v.z; cp[4*t+3] = v.w;
            }
        }
        mat_mul_row_part<4, 7>(cp, sm[1][2], orow, lane);
    }
}

extern "C" void kernel_launch(void* const* d_in, const int* in_sizes, int n_in,
                              void* d_out, int out_size) {
    const float* table = (const float*)d_in[0];   // [32001, 784] fp32
    const int*   sent  = (const int*)d_in[1];     // [2048, 64]  int32
    float*       out   = (float*)d_out;           // [2048, 784] fp32

    w2m_fused_kernel<<<NBATCH, NW * 32>>>(table, sent, out);
}

// round 16
// speedup vs baseline: 1.1936x; 1.0715x over previous
#include <cuda_runtime.h>
#include <cstdint>

#define D       28
#define EMB     784
#define MATB    (EMB * 4)    // 3136 bytes per matrix
#define SLEN    64
#define HALF    16           // words per chain (2 chains of 16 per warp = half sentence)
#define NW      2            // warps per block (one sentence per block)
#define NBATCH  2048

// Per-warp smem: 4 matrix slots of exactly 784 floats (3136 B), contiguous,
// order A0,B0,A1,B1. 3136 mod 128 == 64, so the chain-B base is offset
// 64 mod 128 from chain-A within each parity: the two broadcast addresses of
// a dual LDS.128 hit disjoint bank groups -> conflict-free.
// slot index: parity 0 -> A=0,B=1 ; parity 1 -> A=2,B=3

// ---- packed f32x2 helpers (Blackwell FFMA2 path, PTX-only) ----
__device__ __forceinline__ unsigned long long ffma2(unsigned long long a,
                                                    unsigned long long b,
                                                    unsigned long long c) {
    unsigned long long d;
    asm("fma.rn.f32x2 %0, %1, %2, %3;" : "=l"(d) : "l"(a), "l"(b), "l"(c));
    return d;
}
__device__ __forceinline__ unsigned long long pack2(float x, float y) {
    unsigned long long d;
    asm("mov.b64 %0, {%1, %2};" : "=l"(d) : "f"(x), "f"(y));
    return d;
}
__device__ __forceinline__ void unpack2(unsigned long long v, float& x, float& y) {
    asm("mov.b64 {%0, %1}, %2;" : "=f"(x), "=f"(y) : "l"(v));
}

__device__ __forceinline__ unsigned smem_u32(const void* p) {
    return (unsigned)__cvta_generic_to_shared(p);
}
__device__ __forceinline__ void mbar_init(unsigned a, unsigned cnt) {
    asm volatile("mbarrier.init.shared.b64 [%0], %1;" :: "r"(a), "r"(cnt) : "memory");
}
__device__ __forceinline__ void mbar_expect_tx(unsigned a, unsigned bytes) {
    asm volatile("mbarrier.arrive.expect_tx.shared.b64 _, [%0], %1;"
                 :: "r"(a), "r"(bytes) : "memory");
}
__device__ __forceinline__ void bulk_g2s(unsigned dst, const void* src, unsigned bytes,
                                         unsigned mbar) {
    asm volatile("cp.async.bulk.shared::cta.global.mbarrier::complete_tx::bytes "
                 "[%0], [%1], %2, [%3];"
                 :: "r"(dst), "l"(src), "r"(bytes), "r"(mbar) : "memory");
}
__device__ __forceinline__ void mbar_wait(unsigned a, unsigned parity) {
    unsigned done;
    asm volatile(
        "{\n\t.reg .pred p;\n\t"
        "mbarrier.try_wait.parity.shared.b64 p, [%1], %2;\n\t"
        "selp.b32 %0, 1, 0, p;\n\t}"
        : "=r"(done) : "r"(a), "r"(parity) : "memory");
    while (!done) {
        asm volatile(
            "{\n\t.reg .pred p;\n\t"
            "mbarrier.try_wait.parity.shared.b64 p, [%1], %2, 0x989680;\n\t"
            "selp.b32 %0, 1, 0, p;\n\t}"
            : "=r"(done) : "r"(a), "r"(parity) : "memory");
    }
}

// Dual-row matmul step, software-pipelined loads (R9 engine — best measured).
__device__ __forceinline__ void mat_mul_dual(float c0[D], float c1[D],
                                             const float* __restrict__ m) {
    unsigned long long a0[D / 2], a1[D / 2];
    ulonglong2 mv[7];
    #pragma unroll
    for (int t = 0; t < 7; t++) mv[t] = ((const ulonglong2*)m)[t];     // row k=0
    #pragma unroll
    for (int j = 0; j < D / 2; j++) { a0[j] = 0ULL; a1[j] = 0ULL; }

    #pragma unroll
    for (int k = 0; k < D; k++) {
        const unsigned long long k0 = pack2(c0[k], c0[k]);
        const unsigned long long k1 = pack2(c1[k], c1[k]);
        const ulonglong2* nxt = (const ulonglong2*)(m + (k + 1) * D);
        #pragma unroll
        for (int t = 0; t < 7; t++) {
            const ulonglong2 cur = mv[t];
            if (k < D - 1) mv[t] = nxt[t];          // prefetch row k+1, slot t
            a0[2*t]     = ffma2(k0, cur.x, a0[2*t]);
            a0[2*t + 1] = ffma2(k0, cur.y, a0[2*t + 1]);
            a1[2*t]     = ffma2(k1, cur.x, a1[2*t]);
            a1[2*t + 1] = ffma2(k1, cur.y, a1[2*t + 1]);
        }
    }
    #pragma unroll
    for (int j = 0; j < D / 2; j++) {
        unpack2(a0[j], c0[2*j], c0[2*j + 1]);
        unpack2(a1[j], c1[2*j], c1[2*j + 1]);
    }
}

// Mono matmul (row per lane, uniform broadcast of M from smem).
__device__ __forceinline__ void mat_mul_row(float c[D], const float* __restrict__ m,
                                            int lane) {
    if (lane < D) {
        unsigned long long acc[D / 2];
        #pragma unroll
        for (int j = 0; j < D / 2; j++) acc[j] = 0ULL;
        #pragma unroll
        for (int k = 0; k < D; k++) {
            const unsigned long long ck = pack2(c[k], c[k]);
            const ulonglong2* mr = (const ulonglong2*)(m + k * D);
            #pragma unroll
            for (int t = 0; t < 7; t++) {
                ulonglong2 mv = mr[t];
                acc[2*t]     = ffma2(ck, mv.x, acc[2*t]);
                acc[2*t + 1] = ffma2(ck, mv.y, acc[2*t + 1]);
            }
        }
        #pragma unroll
        for (int j = 0; j < D / 2; j++) unpack2(acc[j], c[2*j], c[2*j + 1]);
    }
}

// Partial mono over j-chunks [TLO, THI): computes columns [4*TLO, 4*THI) of
// row `lane` of (c @ M) and stores them straight to orow (16B-aligned chunks).
template <int TLO, int THI>
__device__ __forceinline__ void mat_mul_row_part(const float c[D],
                                                 const float* __restrict__ m,
                                                 float* __restrict__ orow, int lane) {
    if (lane < D) {
        unsigned long long acc[2 * (THI - TLO)];
        #pragma unroll
        for (int j = 0; j < 2 * (THI - TLO); j++) acc[j] = 0ULL;
        #pragma unroll
        for (int k = 0; k < D; k++) {
            const unsigned long long ck = pack2(c[k], c[k]);
            const ulonglong2* mr = (const ulonglong2*)(m + k * D);
            #pragma unroll
            for (int t = TLO; t < THI; t++) {
                ulonglong2 mv = mr[t];
                acc[2*(t-TLO)]     = ffma2(ck, mv.x, acc[2*(t-TLO)]);
                acc[2*(t-TLO) + 1] = ffma2(ck, mv.y, acc[2*(t-TLO) + 1]);
            }
        }
        #pragma unroll
        for (int t = TLO; t < THI; t++) {
            float x0, x1, x2, x3;
            unpack2(acc[2*(t-TLO)],     x0, x1);
            unpack2(acc[2*(t-TLO) + 1], x2, x3);
            *(float4*)(orow + 4 * t) = make_float4(x0, x1, x2, x3);
        }
    }
}

// publish this lane's two chain-result rows into an smem matrix slot
__device__ __forceinline__ void publish_dual(const float c0[D], const float c1[D],
                                             float* dst, int g) {
    float* r0 = dst + g * D;
    float* r1 = dst + (g + 14) * D;
    #pragma unroll
    for (int t = 0; t < 7; t++) {
        *(float4*)(r0 + 4 * t) = make_float4(c0[4*t], c0[4*t+1], c0[4*t+2], c0[4*t+3]);
        *(float4*)(r1 + 4 * t) = make_float4(c1[4*t], c1[4*t+1], c1[4*t+2], c1[4*t+3]);
    }
}

// publish this lane's single row (mono result) into an smem matrix slot
__device__ __forceinline__ void store_rows(const float c[D], float* dst, int lane) {
    if (lane < D) {
        float* o = dst + lane * D;
        #pragma unroll
        for (int t = 0; t < 7; t++)
            *(float4*)(o + 4 * t) = make_float4(c[4*t], c[4*t+1], c[4*t+2], c[4*t+3]);
    }
}

// ---- fused kernel: 2048 blocks x 2 warps; warp = half-sentence, in-block combine ----
__global__ __launch_bounds__(NW * 32, 8)
void w2m_fused_kernel(const float* __restrict__ table,
                      const int*   __restrict__ sent,
                      float*       __restrict__ out) {
    // [warp][slot][784]: slot order A0,B0,A1,B1 (3136 B apart -> 64 mod 128)
    __shared__ __align__(16) float sm[NW][4][EMB];
    __shared__ __align__(8)  unsigned long long mbar[NW][2];

    const int tid  = threadIdx.x;
    const int warp = tid >> 5;
    const int lane = tid & 31;
    const int b    = blockIdx.x;
    const int* si  = sent + b * SLEN + warp * 32;   // 32 words: 2 chains of 16

    if (tid < NW * 2) mbar_init(smem_u32(&mbar[tid >> 1][tid & 1]), 1);
    __syncthreads();

    const int  grp   = (lane >= 14) ? 1 : 0;                 // 0: chain A, 1: chain B
    const int  g     = (lane < 14) ? lane : (lane < 28 ? lane - 14 : 0);
    const bool valid = (lane < 28);
    float (* const wsm)[EMB] = sm[warp];

    // ---- init: cur = first matrix of the chain (rows g and g+14) ----
    float c0[D], c1[D];
    {
        const float* src = table + (size_t)(grp ? si[HALF] : si[0]) * EMB;
        const float* p0 = src + g * D;
        const float* p1 = p0 + 14 * D;
        #pragma unroll
        for (int t = 0; t < 7; t++) {
            float4 v0 = __ldg((const float4*)(p0 + 4 * t));
            float4 v1 = __ldg((const float4*)(p1 + 4 * t));
            c0[4*t] = v0.x; c0[4*t+1] = v0.y; c0[4*t+2] = v0.z; c0[4*t+3] = v0.w;
            c1[4*t] = v1.x; c1[4*t+1] = v1.y; c1[4*t+2] = v1.z; c1[4*t+3] = v1.w;
        }
    }

    // ---- prologue: prefetch step-1 matrices (both chains) into parity-1 slots ----
    if (lane == 0) {
        const unsigned mb = smem_u32(&mbar[warp][1]);
        mbar_expect_tx(mb, 2 * MATB);
        bulk_g2s(smem_u32(wsm[2]), table + (size_t)si[1] * EMB, MATB, mb);
        bulk_g2s(smem_u32(wsm[3]), table + (size_t)si[HALF + 1] * EMB, MATB, mb);
    }

    int ph0 = 0, ph1 = 0;
    #pragma unroll 1
    for (int s = 1; s < HALF; ++s) {
        const int par = s & 1;
        if (s + 1 < HALF && lane == 0) {
            const int np = (s + 1) & 1;
            const unsigned mb = smem_u32(&mbar[warp][np]);
            mbar_expect_tx(mb, 2 * MATB);
            bulk_g2s(smem_u32(wsm[np ? 2 : 0]),
                     table + (size_t)si[s + 1] * EMB, MATB, mb);
            bulk_g2s(smem_u32(wsm[np ? 3 : 1]),
                     table + (size_t)si[HALF + s + 1] * EMB, MATB, mb);
        }
        if (par) { mbar_wait(smem_u32(&mbar[warp][1]), ph1); ph1 ^= 1; }
        else     { mbar_wait(smem_u32(&mbar[warp][0]), ph0); ph0 ^= 1; }

        const float* m = wsm[(par ? 2 : 0) + grp];   // A: slot 0/2, B: slot 1/3
        mat_mul_dual(c0, c1, m);
        __syncwarp();
    }

    // ---- intra-warp tail: P_w = P_chainA @ P_chainB (mono) ----
    // last dual step s=15 (odd) read parity-1 slots (2,3) -> slots 0,1 free
    if (valid) publish_dual(c0, c1, wsm[grp], g);    // A -> slot0, B -> slot1
    __syncwarp();

    float c[D];
    if (lane < D) {
        const float* p = wsm[0] + lane * D;
        #pragma unroll
        for (int t = 0; t < 7; t++) {
            float4 v = *(const float4*)(p + 4 * t);
            c[4*t] = v.x; c[4*t+1] = v.y; c[4*t+2] = v.z; c[4*t+3] = v.w;
        }
    }
    mat_mul_row(c, wsm[1], lane);                    // c = P_w (row `lane`)

    // ---- in-block combine, column-split across warps: out = P_0 @ P_1 ----
    // Both warps publish P_w into their own slot 2 (free after step 15).
    store_rows(c, wsm[2], lane);
    __syncthreads();

    float* const orow = out + (size_t)b * EMB + lane * D;
    if (warp == 0) {
        // warp 0: has P_0 row `lane` in c; columns 0..15 against P_1
        mat_mul_row_part<0, 4>(c, sm[1][2], orow, lane);
    } else {
        // warp 1: load P_0 row `lane`, columns 16..27 against P_1 (own slot)
        float cp[D];
        if (lane < D) {
            const float* p = sm[0][2] + lane * D;
            #pragma unroll
            for (int t = 0; t < 7; t++) {
                float4 v = *(const float4*)(p + 4 * t);
                cp[4*t] = v.x; cp[4*t+1] = v.y; cp[4*t+2] = v.z; cp[4*t+3] = v.w;
            }
        }
        mat_mul_row_part<4, 7>(cp, sm[1][2], orow, lane);
    }
}

extern "C" void kernel_launch(void* const* d_in, const int* in_sizes, int n_in,
                              void* d_out, int out_size) {
    const float* table = (const float*)d_in[0];   // [32001, 784] fp32
    const int*   sent  = (const int*)d_in[1];     // [2048, 64]  int32
    float*       out   = (float*)d_out;           // [2048, 784] fp32

    w2m_fused_kernel<<<NBATCH, NW * 32>>>(table, sent, out);
}